// round 14
// baseline (speedup 1.0000x reference)
#include <cuda_runtime.h>
#include <cuda_bf16.h>
#include <math.h>
#include <stdint.h>

#define NTOK 16384
#define CDIM 2048
#define NE   16
#define DE   128
#define HDIM 512

// ---------------- device scratch (statics: no allocs allowed) ---------------
__device__ int g_count[NE];
__device__ int g_list[NE][NTOK];
// pre-converted bf16 hi/lo weights (8 MB total)
__device__ __nv_bfloat16 g_fch[NE * HDIM * DE];
__device__ __nv_bfloat16 g_fcl[NE * HDIM * DE];
__device__ __nv_bfloat16 g_pjh[NE * 4 * DE * 128];  // [e][hc][dd][h_local]
__device__ __nv_bfloat16 g_pjl[NE * 4 * DE * 128];

__global__ void cleanup_kernel() {
    if (threadIdx.x < NE) g_count[threadIdx.x] = 0;
}
// profiling landing pad: ncu captures the 4th launch; this makes it expert_kernel
__global__ void dummy_kernel() {}

// ---------------- weight pre-conversion ------------------------------------
__device__ __forceinline__ unsigned long long split4(float4 v,
                                                     unsigned long long& lo64) {
    __nv_bfloat16 h0 = __float2bfloat16_rn(v.x), h1 = __float2bfloat16_rn(v.y);
    __nv_bfloat16 h2 = __float2bfloat16_rn(v.z), h3 = __float2bfloat16_rn(v.w);
    __nv_bfloat162 lA = __floats2bfloat162_rn(v.x - __bfloat162float(h0),
                                              v.y - __bfloat162float(h1));
    __nv_bfloat162 lB = __floats2bfloat162_rn(v.z - __bfloat162float(h2),
                                              v.w - __bfloat162float(h3));
    __nv_bfloat162 hA; hA.x = h0; hA.y = h1;
    __nv_bfloat162 hB; hB.x = h2; hB.y = h3;
    lo64 = (unsigned long long)(*(unsigned int*)&lA)
         | ((unsigned long long)(*(unsigned int*)&lB) << 32);
    return (unsigned long long)(*(unsigned int*)&hA)
         | ((unsigned long long)(*(unsigned int*)&hB) << 32);
}

__global__ __launch_bounds__(256) void wconv_kernel(
    const float* __restrict__ fcw, const float* __restrict__ pjw)
{
    int i = blockIdx.x * 256 + threadIdx.x;   // float4 index, 0..262143
    {
        float4 v = ((const float4*)fcw)[i];
        unsigned long long lo, hi = split4(v, lo);
        ((unsigned long long*)g_fch)[i] = hi;
        ((unsigned long long*)g_fcl)[i] = lo;
    }
    {
        float4 v = ((const float4*)pjw)[i];
        int h0 = (i & 127) * 4;
        int dd = (i >> 7) & 127;
        int e  = i >> 14;
        size_t dst = ((((size_t)(e * 4 + (h0 >> 7)) * 128 + dd) * 128
                       + (h0 & 127)) >> 2);
        unsigned long long lo, hi = split4(v, lo);
        ((unsigned long long*)g_pjh)[dst] = hi;
        ((unsigned long long*)g_pjl)[dst] = lo;
    }
}

// ======================= gate (exact path) ==================================
#define GT  128
#define GKC 64
__device__ __forceinline__ unsigned long long pk2(float a, float b) {
    unsigned long long r;
    asm("mov.b64 %0, {%1, %2};" : "=l"(r) : "f"(a), "f"(b));
    return r;
}
__device__ __forceinline__ void upk2(unsigned long long v, float& a, float& b) {
    asm("mov.b64 {%0, %1}, %2;" : "=f"(a), "=f"(b) : "l"(v));
}
#define FMA2(acc, a, b) \
    asm("fma.rn.f32x2 %0, %1, %2, %0;" : "+l"(acc) : "l"(a), "l"(b))

__global__ __launch_bounds__(128) void gate_kernel(
    const float* __restrict__ x, const float* __restrict__ gw,
    const float* __restrict__ gb, float* __restrict__ out)
{
    __shared__ float xs[GKC][GT + 4];
    __shared__ float ws[GKC][NE];
    __shared__ unsigned char act[GT][NE];

    const int tid  = threadIdx.x;
    const int t0   = blockIdx.x * GT;
    const int tok4 = (tid & 31) * 4;
    const int e4   = (tid >> 5) * 4;

    double acc[4][4];
#pragma unroll
    for (int i = 0; i < 4; i++)
#pragma unroll
        for (int j = 0; j < 4; j++) acc[i][j] = 0.0;

    for (int c0 = 0; c0 < CDIM; c0 += GKC) {
        for (int i = tid; i < GT * GKC; i += 128) {
            int t = i >> 6, c = i & 63;
            xs[c][t] = x[(size_t)(t0 + t) * CDIM + c0 + c];
        }
        for (int i = tid; i < NE * GKC; i += 128) {
            int e = i >> 6, c = i & 63;
            ws[c][e] = gw[e * CDIM + c0 + c];
        }
        __syncthreads();

        unsigned long long f2[4][2];
#pragma unroll
        for (int i = 0; i < 4; i++) { f2[i][0] = 0ull; f2[i][1] = 0ull; }

#pragma unroll 8
        for (int c = 0; c < GKC; c++) {
            float4 xv = *(const float4*)&xs[c][tok4];
            ulonglong2 wv = *(const ulonglong2*)&ws[c][e4];
            unsigned long long b0 = pk2(xv.x, xv.x);
            unsigned long long b1 = pk2(xv.y, xv.y);
            unsigned long long b2 = pk2(xv.z, xv.z);
            unsigned long long b3 = pk2(xv.w, xv.w);
            FMA2(f2[0][0], b0, wv.x); FMA2(f2[0][1], b0, wv.y);
            FMA2(f2[1][0], b1, wv.x); FMA2(f2[1][1], b1, wv.y);
            FMA2(f2[2][0], b2, wv.x); FMA2(f2[2][1], b2, wv.y);
            FMA2(f2[3][0], b3, wv.x); FMA2(f2[3][1], b3, wv.y);
        }
#pragma unroll
        for (int i = 0; i < 4; i++)
#pragma unroll
            for (int jp = 0; jp < 2; jp++) {
                float lo, hi; upk2(f2[i][jp], lo, hi);
                acc[i][2 * jp]     += (double)lo;
                acc[i][2 * jp + 1] += (double)hi;
            }
        __syncthreads();
    }

#pragma unroll
    for (int i = 0; i < 4; i++)
#pragma unroll
        for (int j = 0; j < 4; j++) {
            float l = (float)acc[i][j] + gb[e4 + j];
            act[tok4 + i][e4 + j] = (l > 0.0f) ? 1 : 0;
        }
    __syncthreads();

    for (int i = tid; i < GT * NE * (DE / 4); i += 128) {
        int pair = i >> 5, q = i & 31;
        int t = pair >> 4, e = pair & 15;
        if (!act[t][e]) {
            float4 z = make_float4(0.f, 0.f, 0.f, 0.f);
            *(float4*)&out[(size_t)(t0 + t) * CDIM + e * DE + q * 4] = z;
        }
    }
    if (tid < NE) {
        int e = tid, cnt = 0;
        for (int t = 0; t < GT; t++) cnt += act[t][e];
        int base = atomicAdd(&g_count[e], cnt);
        for (int t = 0; t < GT; t++)
            if (act[t][e]) g_list[e][base++] = t0 + t;
    }
}

// ======================= expert MLP: mma.sync + ldmatrix + cp.async =========
#define MT 64
#define ROWB 272                   // row stride bytes (bank-shift 4)
#define A_TILE (64 * ROWB)         // 17408
#define B_TILE (128 * ROWB)        // 34816

#define OFF_A1H 0
#define OFF_A1L (OFF_A1H + A_TILE)
#define OFF_A2H (OFF_A1L + A_TILE)
#define OFF_A2L (OFF_A2H + A_TILE)
#define OFF_FCH (OFF_A2L + A_TILE)
#define OFF_FCL (OFF_FCH + B_TILE)
#define OFF_PJH (OFF_FCL + B_TILE)
#define OFF_PJL (OFF_PJH + B_TILE)
#define OFF_TOK (OFF_PJL + B_TILE)
#define SMEM_TOTAL (OFF_TOK + 256 + 128)

#define CP16(dst, src) \
    asm volatile("cp.async.cg.shared.global [%0], [%1], 16;" \
                 :: "r"(dst), "l"(src))
#define CP_COMMIT() asm volatile("cp.async.commit_group;" ::: "memory")
#define CP_WAIT1()  asm volatile("cp.async.wait_group 1;" ::: "memory")
#define CP_WAIT0()  asm volatile("cp.async.wait_group 0;" ::: "memory")

__device__ __forceinline__ uint32_t smem_u32(const void* p) {
    uint32_t a;
    asm("{ .reg .u64 t; cvta.to.shared.u64 t, %1; cvt.u32.u64 %0, t; }"
        : "=r"(a) : "l"(p));
    return a;
}
__device__ __forceinline__ void mma16816(float* d, const uint32_t* a,
                                         const uint32_t* b) {
    asm volatile(
        "mma.sync.aligned.m16n8k16.row.col.f32.bf16.bf16.f32 "
        "{%0,%1,%2,%3}, {%4,%5,%6,%7}, {%8,%9}, {%0,%1,%2,%3};"
        : "+f"(d[0]), "+f"(d[1]), "+f"(d[2]), "+f"(d[3])
        : "r"(a[0]), "r"(a[1]), "r"(a[2]), "r"(a[3]), "r"(b[0]), "r"(b[1]));
}
__device__ __forceinline__ void ldsm4(uint32_t* r, uint32_t addr) {
    asm volatile("ldmatrix.sync.aligned.m8n8.x4.shared.b16 {%0,%1,%2,%3}, [%4];"
                 : "=r"(r[0]), "=r"(r[1]), "=r"(r[2]), "=r"(r[3]) : "r"(addr));
}
__device__ __forceinline__ uint32_t pack2bf(float a, float b) {
    __nv_bfloat162 p = __floats2bfloat162_rn(a, b);
    return *(uint32_t*)&p;
}

// copy one 128x128 bf16 tile (32 KB contiguous global) to padded smem
__device__ __forceinline__ void tile_cp(uint32_t sdst,
                                        const __nv_bfloat16* gsrc, int tid) {
#pragma unroll
    for (int k = 0; k < 8; k++) {
        int i = tid + k * 256;
        uint32_t d = sdst + (uint32_t)((i >> 4) * ROWB + (i & 15) * 16);
        CP16(d, (const char*)gsrc + (size_t)i * 16);
    }
}

// merged 3-split GEMM over a 128-K chunk: warp tile 32 tok x 32 cols.
// aH/aL: lane-adjusted A bases (hi/lo); bH/bL: lane-adjusted B bases.
// Per kt: 8 LDSM.x4 + 24 HMMA (Ah*Bh + Ah*Bl + Al*Bh).
__device__ __forceinline__ void gemm_3split(uint32_t aH, uint32_t aL,
                                            uint32_t bH, uint32_t bL,
                                            float (*d)[4]) {
#pragma unroll
    for (int kt = 0; kt < 8; kt++) {
        uint32_t ah[2][4], al[2][4], bh[2][4], bl[2][4];
        ldsm4(ah[0], aH);            ldsm4(ah[1], aH + 16 * ROWB);
        ldsm4(al[0], aL);            ldsm4(al[1], aL + 16 * ROWB);
        ldsm4(bh[0], bH);            ldsm4(bh[1], bH + 16 * ROWB);
        ldsm4(bl[0], bL);            ldsm4(bl[1], bL + 16 * ROWB);
        aH += 32; aL += 32; bH += 32; bL += 32;
#pragma unroll
        for (int nt = 0; nt < 4; nt++) {
            const int p = nt >> 1, o = nt & 1;
            uint32_t vh[2] = { bh[p][o], bh[p][2 + o] };
            uint32_t vl[2] = { bl[p][o], bl[p][2 + o] };
            mma16816(d[nt],     ah[0], vh);
            mma16816(d[4 + nt], ah[1], vh);
            mma16816(d[nt],     ah[0], vl);
            mma16816(d[4 + nt], ah[1], vl);
            mma16816(d[nt],     al[0], vh);
            mma16816(d[4 + nt], al[1], vh);
        }
    }
}

__global__ __launch_bounds__(256) void expert_kernel(
    const float* __restrict__ x,
    const float* __restrict__ fcb, const float* __restrict__ pjb,
    float* __restrict__ out)
{
    const int e   = blockIdx.y;
    const int cnt = g_count[e];
    const int i0  = blockIdx.x * MT;
    if (i0 >= cnt) return;

    extern __shared__ char sm[];
    const uint32_t smb = smem_u32(sm);
    int* toks = (int*)(sm + OFF_TOK);

    const int tid  = threadIdx.x;
    const int wid  = tid >> 5;
    const int lane = tid & 31;
    const int g    = lane >> 2;
    const int c    = lane & 3;
    const int row0 = 32 * (wid & 1);
    const int col0 = 32 * (wid >> 1);
    // ldmatrix lane address components
    const int lrow = lane & 15;
    const int lcol = (lane >> 4) * 16;
    const uint32_t aoff = (uint32_t)((row0 + lrow) * ROWB + lcol);
    const uint32_t boff = (uint32_t)((col0 + lrow) * ROWB + lcol);

    // prologue: prefetch fc[0] (group 0) and pj[0] (group 1)
    tile_cp(smb + OFF_FCH, g_fch + ((size_t)e * HDIM) * DE, tid);
    tile_cp(smb + OFF_FCL, g_fcl + ((size_t)e * HDIM) * DE, tid);
    CP_COMMIT();
    tile_cp(smb + OFF_PJH, g_pjh + (size_t)(e * 4) * DE * 128, tid);
    tile_cp(smb + OFF_PJL, g_pjl + (size_t)(e * 4) * DE * 128, tid);
    CP_COMMIT();

    if (tid < MT) {
        int idx = i0 + tid;
        toks[tid] = (idx < cnt) ? g_list[e][idx] : -1;
    }
    __syncthreads();

    // A1: gather x strided channels, hi/lo split
    for (int i = tid; i < MT * DE; i += 256) {
        int j = i & 63, d = i >> 6;
        int t = toks[j];
        float f = (t >= 0) ? x[(size_t)t * CDIM + d * NE + e] : 0.0f;
        __nv_bfloat16 hb = __float2bfloat16_rn(f);
        uint32_t o = (uint32_t)(j * ROWB + d * 2);
        *(__nv_bfloat16*)(sm + OFF_A1H + o) = hb;
        *(__nv_bfloat16*)(sm + OFF_A1L + o) =
            __float2bfloat16_rn(f - __bfloat162float(hb));
    }

    float d2[8][4];
#pragma unroll
    for (int i = 0; i < 8; i++)
#pragma unroll
        for (int q = 0; q < 4; q++) d2[i][q] = 0.0f;

    for (int hc = 0; hc < 4; hc++) {
        CP_WAIT1();          // fc[hc] resident (pj[hc] may still fly)
        __syncthreads();

        float d1[8][4];
#pragma unroll
        for (int i = 0; i < 8; i++)
#pragma unroll
            for (int q = 0; q < 4; q++) d1[i][q] = 0.0f;
        gemm_3split(smb + OFF_A1H + aoff, smb + OFF_A1L + aoff,
                    smb + OFF_FCH + boff, smb + OFF_FCL + boff, d1);
        __syncthreads();     // done reading FC + prev A2

        if (hc < 3) {        // prefetch fc[hc+1]
            size_t b = ((size_t)e * HDIM + (hc + 1) * 128) * DE;
            tile_cp(smb + OFF_FCH, g_fch + b, tid);
            tile_cp(smb + OFF_FCL, g_fcl + b, tid);
            CP_COMMIT();
        }

        // epilogue: bias + exact gelu -> A2 hi/lo
#pragma unroll
        for (int mt = 0; mt < 2; mt++)
#pragma unroll
            for (int nt = 0; nt < 4; nt++) {
                float* dv = d1[mt * 4 + nt];
                int col = col0 + nt * 8 + 2 * c;
                float b0 = fcb[e * HDIM + hc * 128 + col];
                float b1 = fcb[e * HDIM + hc * 128 + col + 1];
#pragma unroll
                for (int hrow = 0; hrow < 2; hrow++) {
                    int r = row0 + 16 * mt + g + 8 * hrow;
                    float v0 = dv[2 * hrow] + b0;
                    float v1 = dv[2 * hrow + 1] + b1;
                    v0 = 0.5f * v0 * (1.0f + erff(v0 * 0.70710678118654752440f));
                    v1 = 0.5f * v1 * (1.0f + erff(v1 * 0.70710678118654752440f));
                    __nv_bfloat16 h0 = __float2bfloat16_rn(v0);
                    __nv_bfloat16 h1 = __float2bfloat16_rn(v1);
                    uint32_t o = (uint32_t)(r * ROWB + col * 2);
                    *(uint32_t*)(sm + OFF_A2H + o) =
                        pack2bf(__bfloat162float(h0), __bfloat162float(h1));
                    *(uint32_t*)(sm + OFF_A2L + o) =
                        pack2bf(v0 - __bfloat162float(h0),
                                v1 - __bfloat162float(h1));
                }
            }

        if (hc < 3) { CP_WAIT1(); } else { CP_WAIT0(); }  // pj[hc] resident
        __syncthreads();     // + A2 visible

        gemm_3split(smb + OFF_A2H + aoff, smb + OFF_A2L + aoff,
                    smb + OFF_PJH + boff, smb + OFF_PJL + boff, d2);
        __syncthreads();     // done reading PJ

        if (hc < 3) {        // prefetch pj[hc+1]
            size_t b = (size_t)(e * 4 + hc + 1) * DE * 128;
            tile_cp(smb + OFF_PJH, g_pjh + b, tid);
            tile_cp(smb + OFF_PJL, g_pjl + b, tid);
            CP_COMMIT();
        }
    }

    // final: D2 + proj_b -> out (active tokens: gate weight exactly 1)
#pragma unroll
    for (int mt = 0; mt < 2; mt++)
#pragma unroll
        for (int nt = 0; nt < 4; nt++) {
            float* dv = d2[mt * 4 + nt];
            int col = col0 + nt * 8 + 2 * c;
            float b0 = pjb[e * DE + col];
            float b1 = pjb[e * DE + col + 1];
#pragma unroll
            for (int hrow = 0; hrow < 2; hrow++) {
                int r = row0 + 16 * mt + g + 8 * hrow;
                int t = toks[r];
                if (t < 0) continue;
                float2 o;
                o.x = dv[2 * hrow] + b0;
                o.y = dv[2 * hrow + 1] + b1;
                *(float2*)&out[(size_t)t * CDIM + e * DE + col] = o;
            }
        }
}

// ---------------- launch ----------------------------------------------------
extern "C" void kernel_launch(void* const* d_in, const int* in_sizes, int n_in,
                              void* d_out, int out_size)
{
    const float* x   = (const float*)d_in[0];
    const float* gw  = (const float*)d_in[1];
    const float* gb  = (const float*)d_in[2];
    const float* fcw = (const float*)d_in[3];
    const float* fcb = (const float*)d_in[4];
    const float* pjw = (const float*)d_in[5];
    const float* pjb = (const float*)d_in[6];
    float* out = (float*)d_out;

    gate_kernel<<<NTOK / GT, 128>>>(x, gw, gb, out);
    wconv_kernel<<<1024, 256>>>(fcw, pjw);
    dummy_kernel<<<1, 32>>>();   // makes expert_kernel the 4th launch -> ncu lands on it

    cudaFuncSetAttribute(expert_kernel,
                         cudaFuncAttributeMaxDynamicSharedMemorySize,
                         SMEM_TOTAL);
    dim3 grid(NTOK / MT, NE);
    expert_kernel<<<grid, 256, SMEM_TOTAL>>>(x, fcb, pjb, out);

    cleanup_kernel<<<1, 32>>>();
}

// round 15
// speedup vs baseline: 1.3659x; 1.3659x over previous
#include <cuda_runtime.h>
#include <cuda_bf16.h>
#include <math.h>
#include <stdint.h>

#define NTOK 16384
#define CDIM 2048
#define NE   16
#define DE   128
#define HDIM 512

// ---------------- device scratch (statics: no allocs allowed) ---------------
__device__ int g_count[NE];
__device__ int g_list[NE][NTOK];
__device__ __nv_bfloat16 g_fch[NE * HDIM * DE];
__device__ __nv_bfloat16 g_fcl[NE * HDIM * DE];
__device__ __nv_bfloat16 g_pjh[NE * 4 * DE * 128];  // [e][hc][dd][h_local]
__device__ __nv_bfloat16 g_pjl[NE * 4 * DE * 128];

__global__ void cleanup_kernel() {
    if (threadIdx.x < NE) g_count[threadIdx.x] = 0;
}
// keeps expert_kernel as the 4th launch so ncu lands on it
__global__ void dummy_kernel() {}

// ---------------- weight pre-conversion ------------------------------------
__device__ __forceinline__ unsigned long long split4(float4 v,
                                                     unsigned long long& lo64) {
    __nv_bfloat16 h0 = __float2bfloat16_rn(v.x), h1 = __float2bfloat16_rn(v.y);
    __nv_bfloat16 h2 = __float2bfloat16_rn(v.z), h3 = __float2bfloat16_rn(v.w);
    __nv_bfloat162 lA = __floats2bfloat162_rn(v.x - __bfloat162float(h0),
                                              v.y - __bfloat162float(h1));
    __nv_bfloat162 lB = __floats2bfloat162_rn(v.z - __bfloat162float(h2),
                                              v.w - __bfloat162float(h3));
    __nv_bfloat162 hA; hA.x = h0; hA.y = h1;
    __nv_bfloat162 hB; hB.x = h2; hB.y = h3;
    lo64 = (unsigned long long)(*(unsigned int*)&lA)
         | ((unsigned long long)(*(unsigned int*)&lB) << 32);
    return (unsigned long long)(*(unsigned int*)&hA)
         | ((unsigned long long)(*(unsigned int*)&hB) << 32);
}

__global__ __launch_bounds__(256) void wconv_kernel(
    const float* __restrict__ fcw, const float* __restrict__ pjw)
{
    int i = blockIdx.x * 256 + threadIdx.x;   // float4 index, 0..262143
    {
        float4 v = ((const float4*)fcw)[i];
        unsigned long long lo, hi = split4(v, lo);
        ((unsigned long long*)g_fch)[i] = hi;
        ((unsigned long long*)g_fcl)[i] = lo;
    }
    {
        float4 v = ((const float4*)pjw)[i];
        int h0 = (i & 127) * 4;
        int dd = (i >> 7) & 127;
        int e  = i >> 14;
        size_t dst = ((((size_t)(e * 4 + (h0 >> 7)) * 128 + dd) * 128
                       + (h0 & 127)) >> 2);
        unsigned long long lo, hi = split4(v, lo);
        ((unsigned long long*)g_pjh)[dst] = hi;
        ((unsigned long long*)g_pjl)[dst] = lo;
    }
}

// ======================= gate (exact path, high-occupancy) ==================
// GT=64 tokens/block, 256 threads, 256 blocks. Thread = 1 token x 4 experts.
// Per-(t,e) accumulation order identical to prior passing gates:
// fp32 chains over 64-channel chunks, fp64 masters across chunks.
#define GT  64
#define GKC 64
__device__ __forceinline__ unsigned long long pk2(float a, float b) {
    unsigned long long r;
    asm("mov.b64 %0, {%1, %2};" : "=l"(r) : "f"(a), "f"(b));
    return r;
}
__device__ __forceinline__ void upk2(unsigned long long v, float& a, float& b) {
    asm("mov.b64 {%0, %1}, %2;" : "=f"(a), "=f"(b) : "l"(v));
}
#define FMA2(acc, a, b) \
    asm("fma.rn.f32x2 %0, %1, %2, %0;" : "+l"(acc) : "l"(a), "l"(b))

__global__ __launch_bounds__(256) void gate_kernel(
    const float* __restrict__ x, const float* __restrict__ gw,
    const float* __restrict__ gb, float* __restrict__ out)
{
    __shared__ float xs[GKC][GT + 4];
    __shared__ float ws[GKC][NE];
    __shared__ unsigned char act[GT][NE];

    const int tid = threadIdx.x;
    const int t0  = blockIdx.x * GT;
    const int tok = tid & 63;
    const int e4  = (tid >> 6) * 4;

    double acc[4] = {0.0, 0.0, 0.0, 0.0};

    for (int c0 = 0; c0 < CDIM; c0 += GKC) {
        for (int i = tid; i < GT * GKC; i += 256) {
            int t = i >> 6, c = i & 63;
            xs[c][t] = x[(size_t)(t0 + t) * CDIM + c0 + c];
        }
        for (int i = tid; i < NE * GKC; i += 256) {
            int e = i >> 6, c = i & 63;
            ws[c][e] = gw[e * CDIM + c0 + c];
        }
        __syncthreads();

        unsigned long long f2[2] = {0ull, 0ull};
#pragma unroll 16
        for (int c = 0; c < GKC; c++) {
            float xv = xs[c][tok];
            ulonglong2 wv = *(const ulonglong2*)&ws[c][e4];
            unsigned long long bx = pk2(xv, xv);
            FMA2(f2[0], bx, wv.x);
            FMA2(f2[1], bx, wv.y);
        }
#pragma unroll
        for (int jp = 0; jp < 2; jp++) {
            float lo, hi; upk2(f2[jp], lo, hi);
            acc[2 * jp]     += (double)lo;
            acc[2 * jp + 1] += (double)hi;
        }
        __syncthreads();
    }

#pragma unroll
    for (int j = 0; j < 4; j++) {
        float l = (float)acc[j] + gb[e4 + j];
        act[tok][e4 + j] = (l > 0.0f) ? 1 : 0;
    }
    __syncthreads();

    // zero output blocks of inactive (t,e) pairs (out is poisoned)
    for (int i = tid; i < GT * NE * (DE / 4); i += 256) {
        int pair = i >> 5, q = i & 31;
        int t = pair >> 4, e = pair & 15;
        if (!act[t][e]) {
            float4 z = make_float4(0.f, 0.f, 0.f, 0.f);
            *(float4*)&out[(size_t)(t0 + t) * CDIM + e * DE + q * 4] = z;
        }
    }
    if (tid < NE) {
        int e = tid, cnt = 0;
        for (int t = 0; t < GT; t++) cnt += act[t][e];
        int base = atomicAdd(&g_count[e], cnt);
        for (int t = 0; t < GT; t++)
            if (act[t][e]) g_list[e][base++] = t0 + t;
    }
}

// ======================= expert MLP: 512 thr, mma.sync + ldmatrix ===========
// Block = (expert, 64-token tile), 512 threads / 16 warps, occ 25%.
// Warp tile = 16 tok x 32 cols. 3-way bf16 split merged in one kt loop.
#define MT 64
#define ROWB 272                   // row stride bytes (bank-shift 4)
#define A_TILE (64 * ROWB)
#define B_TILE (128 * ROWB)

#define OFF_A1H 0
#define OFF_A1L (OFF_A1H + A_TILE)
#define OFF_A2H (OFF_A1L + A_TILE)
#define OFF_A2L (OFF_A2H + A_TILE)
#define OFF_FCH (OFF_A2L + A_TILE)
#define OFF_FCL (OFF_FCH + B_TILE)
#define OFF_PJH (OFF_FCL + B_TILE)
#define OFF_PJL (OFF_PJH + B_TILE)
#define OFF_TOK (OFF_PJL + B_TILE)
#define SMEM_TOTAL (OFF_TOK + 256 + 128)

#define CP16(dst, src) \
    asm volatile("cp.async.cg.shared.global [%0], [%1], 16;" \
                 :: "r"(dst), "l"(src))
#define CP_COMMIT() asm volatile("cp.async.commit_group;" ::: "memory")
#define CP_WAIT1()  asm volatile("cp.async.wait_group 1;" ::: "memory")
#define CP_WAIT0()  asm volatile("cp.async.wait_group 0;" ::: "memory")

__device__ __forceinline__ uint32_t smem_u32(const void* p) {
    uint32_t a;
    asm("{ .reg .u64 t; cvta.to.shared.u64 t, %1; cvt.u32.u64 %0, t; }"
        : "=r"(a) : "l"(p));
    return a;
}
__device__ __forceinline__ void mma16816(float* d, const uint32_t* a,
                                         const uint32_t* b) {
    asm volatile(
        "mma.sync.aligned.m16n8k16.row.col.f32.bf16.bf16.f32 "
        "{%0,%1,%2,%3}, {%4,%5,%6,%7}, {%8,%9}, {%0,%1,%2,%3};"
        : "+f"(d[0]), "+f"(d[1]), "+f"(d[2]), "+f"(d[3])
        : "r"(a[0]), "r"(a[1]), "r"(a[2]), "r"(a[3]), "r"(b[0]), "r"(b[1]));
}
__device__ __forceinline__ void ldsm4(uint32_t* r, uint32_t addr) {
    asm volatile("ldmatrix.sync.aligned.m8n8.x4.shared.b16 {%0,%1,%2,%3}, [%4];"
                 : "=r"(r[0]), "=r"(r[1]), "=r"(r[2]), "=r"(r[3]) : "r"(addr));
}
__device__ __forceinline__ uint32_t pack2bf(float a, float b) {
    __nv_bfloat162 p = __floats2bfloat162_rn(a, b);
    return *(uint32_t*)&p;
}

// copy one 128x128 bf16 tile (32 KB contiguous global) to padded smem (512 thr)
__device__ __forceinline__ void tile_cp(uint32_t sdst,
                                        const __nv_bfloat16* gsrc, int tid) {
#pragma unroll
    for (int k = 0; k < 4; k++) {
        int i = tid + k * 512;
        uint32_t d = sdst + (uint32_t)((i >> 4) * ROWB + (i & 15) * 16);
        CP16(d, (const char*)gsrc + (size_t)i * 16);
    }
}

// merged 3-split GEMM over 128-K chunk: warp tile 16 tok x 32 cols.
// Per kt: 6 LDSM.x4 + 12 HMMA (Ah*Bh + Ah*Bl + Al*Bh) into 4 accum chains.
__device__ __forceinline__ void gemm_3split(uint32_t aH, uint32_t aL,
                                            uint32_t bH, uint32_t bL,
                                            float (*d)[4]) {
#pragma unroll
    for (int kt = 0; kt < 8; kt++) {
        uint32_t ah[4], al[4], bh[2][4], bl[2][4];
        ldsm4(ah, aH);               ldsm4(al, aL);
        ldsm4(bh[0], bH);            ldsm4(bh[1], bH + 16 * ROWB);
        ldsm4(bl[0], bL);            ldsm4(bl[1], bL + 16 * ROWB);
        aH += 32; aL += 32; bH += 32; bL += 32;
#pragma unroll
        for (int nt = 0; nt < 4; nt++) {
            const int p = nt >> 1, o = nt & 1;
            uint32_t vh[2] = { bh[p][o], bh[p][2 + o] };
            uint32_t vl[2] = { bl[p][o], bl[p][2 + o] };
            mma16816(d[nt], ah, vh);
            mma16816(d[nt], ah, vl);
            mma16816(d[nt], al, vh);
        }
    }
}

__global__ __launch_bounds__(512) void expert_kernel(
    const float* __restrict__ x,
    const float* __restrict__ fcb, const float* __restrict__ pjb,
    float* __restrict__ out)
{
    const int e   = blockIdx.y;
    const int cnt = g_count[e];
    const int i0  = blockIdx.x * MT;
    if (i0 >= cnt) return;

    extern __shared__ char sm[];
    const uint32_t smb = smem_u32(sm);
    int* toks = (int*)(sm + OFF_TOK);

    const int tid  = threadIdx.x;
    const int wid  = tid >> 5;
    const int lane = tid & 31;
    const int g    = lane >> 2;
    const int c    = lane & 3;
    const int row0 = 16 * (wid & 3);   // token rows (4 groups of 16)
    const int col0 = 32 * (wid >> 2);  // output cols (4 groups of 32)
    const int lrow = lane & 15;
    const int lcol = (lane >> 4) * 16;
    const uint32_t aoff = (uint32_t)((row0 + lrow) * ROWB + lcol);
    const uint32_t boff = (uint32_t)((col0 + lrow) * ROWB + lcol);

    // prologue: prefetch fc[0] (group 0) and pj[0] (group 1)
    tile_cp(smb + OFF_FCH, g_fch + ((size_t)e * HDIM) * DE, tid);
    tile_cp(smb + OFF_FCL, g_fcl + ((size_t)e * HDIM) * DE, tid);
    CP_COMMIT();
    tile_cp(smb + OFF_PJH, g_pjh + (size_t)(e * 4) * DE * 128, tid);
    tile_cp(smb + OFF_PJL, g_pjl + (size_t)(e * 4) * DE * 128, tid);
    CP_COMMIT();

    if (tid < MT) {
        int idx = i0 + tid;
        toks[tid] = (idx < cnt) ? g_list[e][idx] : -1;
    }
    __syncthreads();

    // A1: gather x strided channels, hi/lo split
    for (int i = tid; i < MT * DE; i += 512) {
        int j = i & 63, d = i >> 6;
        int t = toks[j];
        float f = (t >= 0) ? x[(size_t)t * CDIM + d * NE + e] : 0.0f;
        __nv_bfloat16 hb = __float2bfloat16_rn(f);
        uint32_t o = (uint32_t)(j * ROWB + d * 2);
        *(__nv_bfloat16*)(sm + OFF_A1H + o) = hb;
        *(__nv_bfloat16*)(sm + OFF_A1L + o) =
            __float2bfloat16_rn(f - __bfloat162float(hb));
    }

    float d2[4][4];
#pragma unroll
    for (int i = 0; i < 4; i++)
#pragma unroll
        for (int q = 0; q < 4; q++) d2[i][q] = 0.0f;

    for (int hc = 0; hc < 4; hc++) {
        CP_WAIT1();          // fc[hc] resident (pj[hc] may still fly)
        __syncthreads();

        float d1[4][4];
#pragma unroll
        for (int i = 0; i < 4; i++)
#pragma unroll
            for (int q = 0; q < 4; q++) d1[i][q] = 0.0f;
        gemm_3split(smb + OFF_A1H + aoff, smb + OFF_A1L + aoff,
                    smb + OFF_FCH + boff, smb + OFF_FCL + boff, d1);
        __syncthreads();     // done reading FC + prev A2

        if (hc < 3) {        // prefetch fc[hc+1]
            size_t b = ((size_t)e * HDIM + (hc + 1) * 128) * DE;
            tile_cp(smb + OFF_FCH, g_fch + b, tid);
            tile_cp(smb + OFF_FCL, g_fcl + b, tid);
            CP_COMMIT();
        }

        // epilogue: bias + exact gelu -> A2 hi/lo
#pragma unroll
        for (int nt = 0; nt < 4; nt++) {
            float* dv = d1[nt];
            int col = col0 + nt * 8 + 2 * c;
            float b0 = fcb[e * HDIM + hc * 128 + col];
            float b1 = fcb[e * HDIM + hc * 128 + col + 1];
#pragma unroll
            for (int hrow = 0; hrow < 2; hrow++) {
                int r = row0 + g + 8 * hrow;
                float v0 = dv[2 * hrow] + b0;
                float v1 = dv[2 * hrow + 1] + b1;
                v0 = 0.5f * v0 * (1.0f + erff(v0 * 0.70710678118654752440f));
                v1 = 0.5f * v1 * (1.0f + erff(v1 * 0.70710678118654752440f));
                __nv_bfloat16 h0 = __float2bfloat16_rn(v0);
                __nv_bfloat16 h1 = __float2bfloat16_rn(v1);
                uint32_t o = (uint32_t)(r * ROWB + col * 2);
                *(uint32_t*)(sm + OFF_A2H + o) =
                    pack2bf(__bfloat162float(h0), __bfloat162float(h1));
                *(uint32_t*)(sm + OFF_A2L + o) =
                    pack2bf(v0 - __bfloat162float(h0),
                            v1 - __bfloat162float(h1));
            }
        }

        if (hc < 3) { CP_WAIT1(); } else { CP_WAIT0(); }  // pj[hc] resident
        __syncthreads();     // + A2 visible

        gemm_3split(smb + OFF_A2H + aoff, smb + OFF_A2L + aoff,
                    smb + OFF_PJH + boff, smb + OFF_PJL + boff, d2);
        __syncthreads();     // done reading PJ

        if (hc < 3) {        // prefetch pj[hc+1]
            size_t b = (size_t)(e * 4 + hc + 1) * DE * 128;
            tile_cp(smb + OFF_PJH, g_pjh + b, tid);
            tile_cp(smb + OFF_PJL, g_pjl + b, tid);
            CP_COMMIT();
        }
    }

    // final: D2 + proj_b -> out (active tokens: gate weight exactly 1)
#pragma unroll
    for (int nt = 0; nt < 4; nt++) {
        float* dv = d2[nt];
        int col = col0 + nt * 8 + 2 * c;
        float b0 = pjb[e * DE + col];
        float b1 = pjb[e * DE + col + 1];
#pragma unroll
        for (int hrow = 0; hrow < 2; hrow++) {
            int r = row0 + g + 8 * hrow;
            int t = toks[r];
            if (t < 0) continue;
            float2 o;
            o.x = dv[2 * hrow] + b0;
            o.y = dv[2 * hrow + 1] + b1;
            *(float2*)&out[(size_t)t * CDIM + e * DE + col] = o;
        }
    }
}

// ---------------- launch ----------------------------------------------------
extern "C" void kernel_launch(void* const* d_in, const int* in_sizes, int n_in,
                              void* d_out, int out_size)
{
    const float* x   = (const float*)d_in[0];
    const float* gw  = (const float*)d_in[1];
    const float* gb  = (const float*)d_in[2];
    const float* fcw = (const float*)d_in[3];
    const float* fcb = (const float*)d_in[4];
    const float* pjw = (const float*)d_in[5];
    const float* pjb = (const float*)d_in[6];
    float* out = (float*)d_out;

    gate_kernel<<<NTOK / GT, 256>>>(x, gw, gb, out);
    wconv_kernel<<<1024, 256>>>(fcw, pjw);
    dummy_kernel<<<1, 32>>>();   // expert_kernel stays the 4th launch for ncu

    cudaFuncSetAttribute(expert_kernel,
                         cudaFuncAttributeMaxDynamicSharedMemorySize,
                         SMEM_TOTAL);
    dim3 grid(NTOK / MT, NE);
    expert_kernel<<<grid, 512, SMEM_TOTAL>>>(x, fcb, pjb, out);

    cleanup_kernel<<<1, 32>>>();
}

// round 16
// speedup vs baseline: 1.4252x; 1.0434x over previous
#include <cuda_runtime.h>
#include <cuda_bf16.h>
#include <math.h>
#include <stdint.h>

#define NTOK 16384
#define CDIM 2048
#define NE   16
#define DE   128
#define HDIM 512

// ---------------- device scratch (statics: no allocs allowed) ---------------
__device__ int g_count[NE];
__device__ int g_list[NE][NTOK];
__device__ __nv_bfloat16 g_fch[NE * HDIM * DE];
__device__ __nv_bfloat16 g_fcl[NE * HDIM * DE];
__device__ __nv_bfloat16 g_pjh[NE * 4 * DE * 128];  // [e][hc][dd][h_local]
__device__ __nv_bfloat16 g_pjl[NE * 4 * DE * 128];

__global__ void cleanup_kernel() {
    if (threadIdx.x < NE) g_count[threadIdx.x] = 0;
}
// keeps expert_kernel as the 4th launch so ncu lands on it
__global__ void dummy_kernel() {}

// ---------------- weight pre-conversion ------------------------------------
__device__ __forceinline__ unsigned long long split4(float4 v,
                                                     unsigned long long& lo64) {
    __nv_bfloat16 h0 = __float2bfloat16_rn(v.x), h1 = __float2bfloat16_rn(v.y);
    __nv_bfloat16 h2 = __float2bfloat16_rn(v.z), h3 = __float2bfloat16_rn(v.w);
    __nv_bfloat162 lA = __floats2bfloat162_rn(v.x - __bfloat162float(h0),
                                              v.y - __bfloat162float(h1));
    __nv_bfloat162 lB = __floats2bfloat162_rn(v.z - __bfloat162float(h2),
                                              v.w - __bfloat162float(h3));
    __nv_bfloat162 hA; hA.x = h0; hA.y = h1;
    __nv_bfloat162 hB; hB.x = h2; hB.y = h3;
    lo64 = (unsigned long long)(*(unsigned int*)&lA)
         | ((unsigned long long)(*(unsigned int*)&lB) << 32);
    return (unsigned long long)(*(unsigned int*)&hA)
         | ((unsigned long long)(*(unsigned int*)&hB) << 32);
}

__global__ __launch_bounds__(256) void wconv_kernel(
    const float* __restrict__ fcw, const float* __restrict__ pjw)
{
    int i = blockIdx.x * 256 + threadIdx.x;   // float4 index, 0..262143
    {
        float4 v = ((const float4*)fcw)[i];
        unsigned long long lo, hi = split4(v, lo);
        ((unsigned long long*)g_fch)[i] = hi;
        ((unsigned long long*)g_fcl)[i] = lo;
    }
    {
        float4 v = ((const float4*)pjw)[i];
        int h0 = (i & 127) * 4;
        int dd = (i >> 7) & 127;
        int e  = i >> 14;
        size_t dst = ((((size_t)(e * 4 + (h0 >> 7)) * 128 + dd) * 128
                       + (h0 & 127)) >> 2);
        unsigned long long lo, hi = split4(v, lo);
        ((unsigned long long*)g_pjh)[dst] = hi;
        ((unsigned long long*)g_pjl)[dst] = lo;
    }
}

// ======================= gate (exact path, conflict-free staging) ===========
#define GT  64
#define GKC 64
__device__ __forceinline__ unsigned long long pk2(float a, float b) {
    unsigned long long r;
    asm("mov.b64 %0, {%1, %2};" : "=l"(r) : "f"(a), "f"(b));
    return r;
}
__device__ __forceinline__ void upk2(unsigned long long v, float& a, float& b) {
    asm("mov.b64 {%0, %1}, %2;" : "=f"(a), "=f"(b) : "l"(v));
}
#define FMA2(acc, a, b) \
    asm("fma.rn.f32x2 %0, %1, %2, %0;" : "+l"(acc) : "l"(a), "l"(b))

__global__ __launch_bounds__(256) void gate_kernel(
    const float* __restrict__ x, const float* __restrict__ gw,
    const float* __restrict__ gb, float* __restrict__ out)
{
    __shared__ float xs[GKC][GT + 1];   // stride 65 words: bank = c + t, conflict-free
    __shared__ float ws[GKC][NE];
    __shared__ unsigned char act[GT][NE];

    const int tid = threadIdx.x;
    const int t0  = blockIdx.x * GT;
    const int tok = tid & 63;
    const int e4  = (tid >> 6) * 4;

    double acc[4] = {0.0, 0.0, 0.0, 0.0};

    for (int c0 = 0; c0 < CDIM; c0 += GKC) {
        for (int i = tid; i < GT * GKC; i += 256) {
            int t = i >> 6, c = i & 63;
            xs[c][t] = x[(size_t)(t0 + t) * CDIM + c0 + c];
        }
        for (int i = tid; i < NE * GKC; i += 256) {
            int e = i >> 6, c = i & 63;
            ws[c][e] = gw[e * CDIM + c0 + c];
        }
        __syncthreads();

        unsigned long long f2[2] = {0ull, 0ull};
#pragma unroll 16
        for (int c = 0; c < GKC; c++) {
            float xv = xs[c][tok];
            ulonglong2 wv = *(const ulonglong2*)&ws[c][e4];
            unsigned long long bx = pk2(xv, xv);
            FMA2(f2[0], bx, wv.x);
            FMA2(f2[1], bx, wv.y);
        }
#pragma unroll
        for (int jp = 0; jp < 2; jp++) {
            float lo, hi; upk2(f2[jp], lo, hi);
            acc[2 * jp]     += (double)lo;
            acc[2 * jp + 1] += (double)hi;
        }
        __syncthreads();
    }

#pragma unroll
    for (int j = 0; j < 4; j++) {
        float l = (float)acc[j] + gb[e4 + j];
        act[tok][e4 + j] = (l > 0.0f) ? 1 : 0;
    }
    __syncthreads();

    for (int i = tid; i < GT * NE * (DE / 4); i += 256) {
        int pair = i >> 5, q = i & 31;
        int t = pair >> 4, e = pair & 15;
        if (!act[t][e]) {
            float4 z = make_float4(0.f, 0.f, 0.f, 0.f);
            *(float4*)&out[(size_t)(t0 + t) * CDIM + e * DE + q * 4] = z;
        }
    }
    if (tid < NE) {
        int e = tid, cnt = 0;
        for (int t = 0; t < GT; t++) cnt += act[t][e];
        int base = atomicAdd(&g_count[e], cnt);
        for (int t = 0; t < GT; t++)
            if (act[t][e]) g_list[e][base++] = t0 + t;
    }
}

// ======================= expert MLP: MT=128, warp tile 32x32 ================
// Block = (expert, 128-token tile), 512 threads / 16 warps (4 row x 4 col).
// Single-buffered B (FC then PJ per hc); PJ load overlaps gelu epilogue.
// 3-way bf16 split merged in one kt loop: 8 LDSM.x4 + 24 HMMA per kt.
#define MT 128
#define ROWB 272                   // row stride bytes (bank-shift 4)
#define A_TILE (128 * ROWB)        // 34816
#define B_TILE (128 * ROWB)        // 34816

#define OFF_A1H 0
#define OFF_A1L (OFF_A1H + A_TILE)
#define OFF_A2H (OFF_A1L + A_TILE)
#define OFF_A2L (OFF_A2H + A_TILE)
#define OFF_BH  (OFF_A2L + A_TILE)
#define OFF_BL  (OFF_BH  + B_TILE)
#define OFF_TOK (OFF_BL  + B_TILE)
#define SMEM_TOTAL (OFF_TOK + 512 + 128)   // ~209.5 KB

#define CP16(dst, src) \
    asm volatile("cp.async.cg.shared.global [%0], [%1], 16;" \
                 :: "r"(dst), "l"(src))
#define CP_COMMIT() asm volatile("cp.async.commit_group;" ::: "memory")
#define CP_WAIT0()  asm volatile("cp.async.wait_group 0;" ::: "memory")

__device__ __forceinline__ uint32_t smem_u32(const void* p) {
    uint32_t a;
    asm("{ .reg .u64 t; cvta.to.shared.u64 t, %1; cvt.u32.u64 %0, t; }"
        : "=r"(a) : "l"(p));
    return a;
}
__device__ __forceinline__ void mma16816(float* d, const uint32_t* a,
                                         const uint32_t* b) {
    asm volatile(
        "mma.sync.aligned.m16n8k16.row.col.f32.bf16.bf16.f32 "
        "{%0,%1,%2,%3}, {%4,%5,%6,%7}, {%8,%9}, {%0,%1,%2,%3};"
        : "+f"(d[0]), "+f"(d[1]), "+f"(d[2]), "+f"(d[3])
        : "r"(a[0]), "r"(a[1]), "r"(a[2]), "r"(a[3]), "r"(b[0]), "r"(b[1]));
}
__device__ __forceinline__ void ldsm4(uint32_t* r, uint32_t addr) {
    asm volatile("ldmatrix.sync.aligned.m8n8.x4.shared.b16 {%0,%1,%2,%3}, [%4];"
                 : "=r"(r[0]), "=r"(r[1]), "=r"(r[2]), "=r"(r[3]) : "r"(addr));
}
__device__ __forceinline__ uint32_t pack2bf(float a, float b) {
    __nv_bfloat162 p = __floats2bfloat162_rn(a, b);
    return *(uint32_t*)&p;
}

// copy one 128x128 bf16 tile (32 KB contiguous global) to padded smem (512 thr)
__device__ __forceinline__ void tile_cp(uint32_t sdst,
                                        const __nv_bfloat16* gsrc, int tid) {
#pragma unroll
    for (int k = 0; k < 4; k++) {
        int i = tid + k * 512;
        uint32_t d = sdst + (uint32_t)((i >> 4) * ROWB + (i & 15) * 16);
        CP16(d, (const char*)gsrc + (size_t)i * 16);
    }
}

// merged 3-split GEMM over 128-K chunk: warp tile 32 tok x 32 cols.
// Per kt: 8 LDSM.x4 + 24 HMMA into 8 independent 3-deep chains.
__device__ __forceinline__ void gemm_3split(uint32_t aH, uint32_t aL,
                                            uint32_t bH, uint32_t bL,
                                            float (*d)[4]) {
#pragma unroll
    for (int kt = 0; kt < 8; kt++) {
        uint32_t ah[2][4], al[2][4], bh[2][4], bl[2][4];
        ldsm4(ah[0], aH);            ldsm4(ah[1], aH + 16 * ROWB);
        ldsm4(al[0], aL);            ldsm4(al[1], aL + 16 * ROWB);
        ldsm4(bh[0], bH);            ldsm4(bh[1], bH + 16 * ROWB);
        ldsm4(bl[0], bL);            ldsm4(bl[1], bL + 16 * ROWB);
        aH += 32; aL += 32; bH += 32; bL += 32;
#pragma unroll
        for (int nt = 0; nt < 4; nt++) {
            const int p = nt >> 1, o = nt & 1;
            uint32_t vh[2] = { bh[p][o], bh[p][2 + o] };
            uint32_t vl[2] = { bl[p][o], bl[p][2 + o] };
            mma16816(d[nt],     ah[0], vh);
            mma16816(d[4 + nt], ah[1], vh);
            mma16816(d[nt],     ah[0], vl);
            mma16816(d[4 + nt], ah[1], vl);
            mma16816(d[nt],     al[0], vh);
            mma16816(d[4 + nt], al[1], vh);
        }
    }
}

__global__ __launch_bounds__(512) void expert_kernel(
    const float* __restrict__ x,
    const float* __restrict__ fcb, const float* __restrict__ pjb,
    float* __restrict__ out)
{
    const int e   = blockIdx.y;
    const int cnt = g_count[e];
    const int i0  = blockIdx.x * MT;
    if (i0 >= cnt) return;

    extern __shared__ char sm[];
    const uint32_t smb = smem_u32(sm);
    int* toks = (int*)(sm + OFF_TOK);

    const int tid  = threadIdx.x;
    const int wid  = tid >> 5;
    const int lane = tid & 31;
    const int g    = lane >> 2;
    const int c    = lane & 3;
    const int row0 = 32 * (wid & 3);   // 4 row groups of 32 tokens
    const int col0 = 32 * (wid >> 2);  // 4 col groups of 32 outputs
    const int lrow = lane & 15;
    const int lcol = (lane >> 4) * 16;
    const uint32_t aoff = (uint32_t)((row0 + lrow) * ROWB + lcol);
    const uint32_t boff = (uint32_t)((col0 + lrow) * ROWB + lcol);

    // prologue: prefetch FC(0)
    tile_cp(smb + OFF_BH, g_fch + ((size_t)e * HDIM) * DE, tid);
    tile_cp(smb + OFF_BL, g_fcl + ((size_t)e * HDIM) * DE, tid);
    CP_COMMIT();

    if (tid < MT) {
        int idx = i0 + tid;
        toks[tid] = (idx < cnt) ? g_list[e][idx] : -1;
    }
    __syncthreads();   // toks visible

    // A1: gather x strided channels, hi/lo split
    for (int i = tid; i < MT * DE; i += 512) {
        int j = i & 127, d = i >> 7;
        int t = toks[j];
        float f = (t >= 0) ? x[(size_t)t * CDIM + d * NE + e] : 0.0f;
        __nv_bfloat16 hb = __float2bfloat16_rn(f);
        uint32_t o = (uint32_t)(j * ROWB + d * 2);
        *(__nv_bfloat16*)(sm + OFF_A1H + o) = hb;
        *(__nv_bfloat16*)(sm + OFF_A1L + o) =
            __float2bfloat16_rn(f - __bfloat162float(hb));
    }

    float d2[8][4];
#pragma unroll
    for (int i = 0; i < 8; i++)
#pragma unroll
        for (int q = 0; q < 4; q++) d2[i][q] = 0.0f;

    for (int hc = 0; hc < 4; hc++) {
        CP_WAIT0();
        __syncthreads();     // FC(hc) + A1 (iter 0) visible

        float d1[8][4];
#pragma unroll
        for (int i = 0; i < 8; i++)
#pragma unroll
            for (int q = 0; q < 4; q++) d1[i][q] = 0.0f;
        gemm_3split(smb + OFF_A1H + aoff, smb + OFF_A1L + aoff,
                    smb + OFF_BH + boff, smb + OFF_BL + boff, d1);
        __syncthreads();     // FC reads done, prev-A2 reads done

        // PJ(hc) load overlaps the gelu epilogue
        {
            size_t b = (size_t)(e * 4 + hc) * DE * 128;
            tile_cp(smb + OFF_BH, g_pjh + b, tid);
            tile_cp(smb + OFF_BL, g_pjl + b, tid);
            CP_COMMIT();
        }

        // epilogue: bias + exact gelu -> A2 hi/lo
#pragma unroll
        for (int mt = 0; mt < 2; mt++)
#pragma unroll
            for (int nt = 0; nt < 4; nt++) {
                float* dv = d1[mt * 4 + nt];
                int col = col0 + nt * 8 + 2 * c;
                float b0 = fcb[e * HDIM + hc * 128 + col];
                float b1 = fcb[e * HDIM + hc * 128 + col + 1];
#pragma unroll
                for (int hrow = 0; hrow < 2; hrow++) {
                    int r = row0 + 16 * mt + g + 8 * hrow;
                    float v0 = dv[2 * hrow] + b0;
                    float v1 = dv[2 * hrow + 1] + b1;
                    v0 = 0.5f * v0 * (1.0f + erff(v0 * 0.70710678118654752440f));
                    v1 = 0.5f * v1 * (1.0f + erff(v1 * 0.70710678118654752440f));
                    __nv_bfloat16 h0 = __float2bfloat16_rn(v0);
                    __nv_bfloat16 h1 = __float2bfloat16_rn(v1);
                    uint32_t o = (uint32_t)(r * ROWB + col * 2);
                    *(uint32_t*)(sm + OFF_A2H + o) =
                        pack2bf(__bfloat162float(h0), __bfloat162float(h1));
                    *(uint32_t*)(sm + OFF_A2L + o) =
                        pack2bf(v0 - __bfloat162float(h0),
                                v1 - __bfloat162float(h1));
                }
            }

        CP_WAIT0();
        __syncthreads();     // PJ ready + A2 visible

        gemm_3split(smb + OFF_A2H + aoff, smb + OFF_A2L + aoff,
                    smb + OFF_BH + boff, smb + OFF_BL + boff, d2);
        __syncthreads();     // PJ reads done -> B free for next FC

        if (hc < 3) {        // FC(hc+1)
            size_t b = ((size_t)e * HDIM + (hc + 1) * 128) * DE;
            tile_cp(smb + OFF_BH, g_fch + b, tid);
            tile_cp(smb + OFF_BL, g_fcl + b, tid);
            CP_COMMIT();
        }
    }

    // final: D2 + proj_b -> out (active tokens: gate weight exactly 1)
#pragma unroll
    for (int mt = 0; mt < 2; mt++)
#pragma unroll
        for (int nt = 0; nt < 4; nt++) {
            float* dv = d2[mt * 4 + nt];
            int col = col0 + nt * 8 + 2 * c;
            float b0 = pjb[e * DE + col];
            float b1 = pjb[e * DE + col + 1];
#pragma unroll
            for (int hrow = 0; hrow < 2; hrow++) {
                int r = row0 + 16 * mt + g + 8 * hrow;
                int t = toks[r];
                if (t < 0) continue;
                float2 o;
                o.x = dv[2 * hrow] + b0;
                o.y = dv[2 * hrow + 1] + b1;
                *(float2*)&out[(size_t)t * CDIM + e * DE + col] = o;
            }
        }
}

// ---------------- launch ----------------------------------------------------
extern "C" void kernel_launch(void* const* d_in, const int* in_sizes, int n_in,
                              void* d_out, int out_size)
{
    const float* x   = (const float*)d_in[0];
    const float* gw  = (const float*)d_in[1];
    const float* gb  = (const float*)d_in[2];
    const float* fcw = (const float*)d_in[3];
    const float* fcb = (const float*)d_in[4];
    const float* pjw = (const float*)d_in[5];
    const float* pjb = (const float*)d_in[6];
    float* out = (float*)d_out;

    gate_kernel<<<NTOK / GT, 256>>>(x, gw, gb, out);
    wconv_kernel<<<1024, 256>>>(fcw, pjw);
    dummy_kernel<<<1, 32>>>();   // expert_kernel stays the 4th launch for ncu

    cudaFuncSetAttribute(expert_kernel,
                         cudaFuncAttributeMaxDynamicSharedMemorySize,
                         SMEM_TOTAL);
    dim3 grid(NTOK / MT, NE);
    expert_kernel<<<grid, 512, SMEM_TOTAL>>>(x, fcb, pjb, out);

    cleanup_kernel<<<1, 32>>>();
}

// round 17
// speedup vs baseline: 1.8142x; 1.2729x over previous
#include <cuda_runtime.h>
#include <cuda_fp16.h>
#include <math.h>
#include <stdint.h>

#define NTOK 16384
#define CDIM 2048
#define NE   16
#define DE   128
#define HDIM 512

// ---------------- device scratch (statics: no allocs allowed) ---------------
__device__ int g_count[NE];
__device__ int g_list[NE][NTOK];
// pre-converted fp16 weights (hi only; activations carry the split) — 4 MB
__device__ __half g_fcw[NE * HDIM * DE];
__device__ __half g_pjw[NE * 4 * DE * 128];   // [e][hc][dd][h_local]

__global__ void cleanup_kernel() {
    if (threadIdx.x < NE) g_count[threadIdx.x] = 0;
}
// keeps expert_kernel as the 4th launch so ncu lands on it
__global__ void dummy_kernel() {}

// ---------------- weight pre-conversion (fp32 -> fp16) ----------------------
__device__ __forceinline__ unsigned long long cvt4h(float4 v) {
    __half2 lo = __floats2half2_rn(v.x, v.y);
    __half2 hi = __floats2half2_rn(v.z, v.w);
    return (unsigned long long)(*(unsigned int*)&lo)
         | ((unsigned long long)(*(unsigned int*)&hi) << 32);
}

__global__ __launch_bounds__(256) void wconv_kernel(
    const float* __restrict__ fcw, const float* __restrict__ pjw)
{
    int i = blockIdx.x * 256 + threadIdx.x;   // float4 index, 0..262143
    {
        float4 v = ((const float4*)fcw)[i];
        ((unsigned long long*)g_fcw)[i] = cvt4h(v);
    }
    {
        float4 v = ((const float4*)pjw)[i];
        int h0 = (i & 127) * 4;
        int dd = (i >> 7) & 127;
        int e  = i >> 14;
        size_t dst = ((((size_t)(e * 4 + (h0 >> 7)) * 128 + dd) * 128
                       + (h0 & 127)) >> 2);
        ((unsigned long long*)g_pjw)[dst] = cvt4h(v);
    }
}

// ======================= gate (exact path, cp.async staged) =================
#define GT  64
#define GKC 64
#define NCH (CDIM / GKC)   // 32 chunks
__device__ __forceinline__ unsigned long long pk2(float a, float b) {
    unsigned long long r;
    asm("mov.b64 %0, {%1, %2};" : "=l"(r) : "f"(a), "f"(b));
    return r;
}
__device__ __forceinline__ void upk2(unsigned long long v, float& a, float& b) {
    asm("mov.b64 {%0, %1}, %2;" : "=f"(a), "=f"(b) : "l"(v));
}
#define FMA2(acc, a, b) \
    asm("fma.rn.f32x2 %0, %1, %2, %0;" : "+l"(acc) : "l"(a), "l"(b))
#define CP4(dst, src) \
    asm volatile("cp.async.ca.shared.global [%0], [%1], 4;" \
                 :: "r"(dst), "l"(src))
#define GCP_COMMIT() asm volatile("cp.async.commit_group;" ::: "memory")
#define GCP_WAIT1()  asm volatile("cp.async.wait_group 1;" ::: "memory")
#define GCP_WAIT0()  asm volatile("cp.async.wait_group 0;" ::: "memory")

__device__ __forceinline__ uint32_t smem_u32(const void* p) {
    uint32_t a;
    asm("{ .reg .u64 t; cvta.to.shared.u64 t, %1; cvt.u32.u64 %0, t; }"
        : "=r"(a) : "l"(p));
    return a;
}

__global__ __launch_bounds__(256) void gate_kernel(
    const float* __restrict__ x, const float* __restrict__ gw,
    const float* __restrict__ gb, float* __restrict__ out)
{
    __shared__ float xs[2][GKC][GT + 1];   // stride 65: conflict-free both phases
    __shared__ float ws[2][GKC][NE];
    __shared__ unsigned char act[GT][NE];

    const int tid = threadIdx.x;
    const int t0  = blockIdx.x * GT;
    const int tok = tid & 63;
    const int e4  = (tid >> 6) * 4;

    // stage chunk k into buffer b via cp.async (identical data placement as LDG path)
    auto stage = [&](int b, int k) {
        int c0 = k * GKC;
        uint32_t xb = smem_u32(&xs[b][0][0]);
        uint32_t wb = smem_u32(&ws[b][0][0]);
#pragma unroll
        for (int q = 0; q < 16; q++) {
            int i = tid + q * 256;
            int t = i >> 6, c = i & 63;
            CP4(xb + (uint32_t)((c * (GT + 1) + t) * 4),
                &x[(size_t)(t0 + t) * CDIM + c0 + c]);
        }
#pragma unroll
        for (int q = 0; q < 4; q++) {
            int i = tid + q * 256;
            int e = i >> 6, c = i & 63;
            CP4(wb + (uint32_t)((c * NE + e) * 4), &gw[e * CDIM + c0 + c]);
        }
        GCP_COMMIT();
    };

    double acc[4] = {0.0, 0.0, 0.0, 0.0};

    stage(0, 0);
    for (int k = 0; k < NCH; k++) {
        if (k + 1 < NCH) stage((k + 1) & 1, k + 1);
        if (k + 1 < NCH) { GCP_WAIT1(); } else { GCP_WAIT0(); }
        __syncthreads();          // chunk k resident, prev compute done

        const int b = k & 1;
        unsigned long long f2[2] = {0ull, 0ull};
#pragma unroll 16
        for (int c = 0; c < GKC; c++) {
            float xv = xs[b][c][tok];
            ulonglong2 wv = *(const ulonglong2*)&ws[b][c][e4];
            unsigned long long bx = pk2(xv, xv);
            FMA2(f2[0], bx, wv.x);
            FMA2(f2[1], bx, wv.y);
        }
#pragma unroll
        for (int jp = 0; jp < 2; jp++) {
            float lo, hi; upk2(f2[jp], lo, hi);
            acc[2 * jp]     += (double)lo;
            acc[2 * jp + 1] += (double)hi;
        }
        __syncthreads();          // buffer b free for chunk k+2
    }

#pragma unroll
    for (int j = 0; j < 4; j++) {
        float l = (float)acc[j] + gb[e4 + j];
        act[tok][e4 + j] = (l > 0.0f) ? 1 : 0;
    }
    __syncthreads();

    // zero output blocks of inactive (t,e) pairs (out is poisoned)
    for (int i = tid; i < GT * NE * (DE / 4); i += 256) {
        int pair = i >> 5, q = i & 31;
        int t = pair >> 4, e = pair & 15;
        if (!act[t][e]) {
            float4 z = make_float4(0.f, 0.f, 0.f, 0.f);
            *(float4*)&out[(size_t)(t0 + t) * CDIM + e * DE + q * 4] = z;
        }
    }
    if (tid < NE) {
        int e = tid, cnt = 0;
        for (int t = 0; t < GT; t++) cnt += act[t][e];
        int base = atomicAdd(&g_count[e], cnt);
        for (int t = 0; t < GT; t++)
            if (act[t][e]) g_list[e][base++] = t0 + t;
    }
}

// ======================= expert MLP: fp16 2-pass split ======================
// Block = (expert, 128-token tile), 512 threads / 16 warps (4 row x 4 col).
// A = activations split hi+lo (fp16, exact to 2^-24); B = weights fp16 hi only.
// D = Ah*B + Al*B  -> error = weight fp16 rounding ~1.4e-4 per GEMM.
// Per kt: 6 LDSM.x4 + 16 HMMA. B double-buffered via cp.async (FC/PJ pipeline).
#define MT 128
#define ROWB 272
#define A_TILE (128 * ROWB)
#define B_TILE (128 * ROWB)

#define OFF_A1H 0
#define OFF_A1L (OFF_A1H + A_TILE)
#define OFF_A2H (OFF_A1L + A_TILE)
#define OFF_A2L (OFF_A2H + A_TILE)
#define OFF_B0  (OFF_A2L + A_TILE)
#define OFF_B1  (OFF_B0  + B_TILE)
#define OFF_TOK (OFF_B1  + B_TILE)
#define SMEM_TOTAL (OFF_TOK + 512 + 128)   // ~204.7 KB

#define CP16(dst, src) \
    asm volatile("cp.async.cg.shared.global [%0], [%1], 16;" \
                 :: "r"(dst), "l"(src))
#define CP_COMMIT() asm volatile("cp.async.commit_group;" ::: "memory")
#define CP_WAIT1()  asm volatile("cp.async.wait_group 1;" ::: "memory")
#define CP_WAIT0()  asm volatile("cp.async.wait_group 0;" ::: "memory")

__device__ __forceinline__ void mma16816(float* d, const uint32_t* a,
                                         const uint32_t* b) {
    asm volatile(
        "mma.sync.aligned.m16n8k16.row.col.f32.f16.f16.f32 "
        "{%0,%1,%2,%3}, {%4,%5,%6,%7}, {%8,%9}, {%0,%1,%2,%3};"
        : "+f"(d[0]), "+f"(d[1]), "+f"(d[2]), "+f"(d[3])
        : "r"(a[0]), "r"(a[1]), "r"(a[2]), "r"(a[3]), "r"(b[0]), "r"(b[1]));
}
__device__ __forceinline__ void ldsm4(uint32_t* r, uint32_t addr) {
    asm volatile("ldmatrix.sync.aligned.m8n8.x4.shared.b16 {%0,%1,%2,%3}, [%4];"
                 : "=r"(r[0]), "=r"(r[1]), "=r"(r[2]), "=r"(r[3]) : "r"(addr));
}
__device__ __forceinline__ uint32_t pack2h(float a, float b) {
    __half2 p = __floats2half2_rn(a, b);
    return *(uint32_t*)&p;
}

// copy one 128x128 fp16 tile (32 KB contiguous global) to padded smem (512 thr)
__device__ __forceinline__ void tile_cp(uint32_t sdst, const __half* gsrc,
                                        int tid) {
#pragma unroll
    for (int k = 0; k < 4; k++) {
        int i = tid + k * 512;
        uint32_t d = sdst + (uint32_t)((i >> 4) * ROWB + (i & 15) * 16);
        CP16(d, (const char*)gsrc + (size_t)i * 16);
    }
}

// 2-pass GEMM over 128-K chunk: warp tile 32 tok x 32 cols.
// Per kt: 6 LDSM.x4 + 16 HMMA into 8 independent 2-deep chains.
__device__ __forceinline__ void gemm_2pass(uint32_t aH, uint32_t aL,
                                           uint32_t bB, float (*d)[4]) {
#pragma unroll
    for (int kt = 0; kt < 8; kt++) {
        uint32_t ah[2][4], al[2][4], bh[2][4];
        ldsm4(ah[0], aH);            ldsm4(ah[1], aH + 16 * ROWB);
        ldsm4(al[0], aL);            ldsm4(al[1], aL + 16 * ROWB);
        ldsm4(bh[0], bB);            ldsm4(bh[1], bB + 16 * ROWB);
        aH += 32; aL += 32; bB += 32;
#pragma unroll
        for (int nt = 0; nt < 4; nt++) {
            const int p = nt >> 1, o = nt & 1;
            uint32_t vh[2] = { bh[p][o], bh[p][2 + o] };
            mma16816(d[nt],     ah[0], vh);
            mma16816(d[nt],     al[0], vh);
            mma16816(d[4 + nt], ah[1], vh);
            mma16816(d[4 + nt], al[1], vh);
        }
    }
}

__global__ __launch_bounds__(512) void expert_kernel(
    const float* __restrict__ x,
    const float* __restrict__ fcb, const float* __restrict__ pjb,
    float* __restrict__ out)
{
    const int e   = blockIdx.y;
    const int cnt = g_count[e];
    const int i0  = blockIdx.x * MT;
    if (i0 >= cnt) return;

    extern __shared__ char sm[];
    const uint32_t smb = smem_u32(sm);
    int* toks = (int*)(sm + OFF_TOK);

    const int tid  = threadIdx.x;
    const int wid  = tid >> 5;
    const int lane = tid & 31;
    const int g    = lane >> 2;
    const int c    = lane & 3;
    const int row0 = 32 * (wid & 3);
    const int col0 = 32 * (wid >> 2);
    const int lrow = lane & 15;
    const int lcol = (lane >> 4) * 16;
    const uint32_t aoff = (uint32_t)((row0 + lrow) * ROWB + lcol);
    const uint32_t boff = (uint32_t)((col0 + lrow) * ROWB + lcol);

    // prologue: FC(0) -> B0 (group), PJ(0) -> B1 (group)
    tile_cp(smb + OFF_B0, g_fcw + ((size_t)e * HDIM) * DE, tid);
    CP_COMMIT();
    tile_cp(smb + OFF_B1, g_pjw + (size_t)(e * 4) * DE * 128, tid);
    CP_COMMIT();

    if (tid < MT) {
        int idx = i0 + tid;
        toks[tid] = (idx < cnt) ? g_list[e][idx] : -1;
    }
    __syncthreads();   // toks visible

    // A1: gather x strided channels, fp16 hi/lo split (exact to 2^-24)
    for (int i = tid; i < MT * DE; i += 512) {
        int j = i & 127, d = i >> 7;
        int t = toks[j];
        float f = (t >= 0) ? x[(size_t)t * CDIM + d * NE + e] : 0.0f;
        __half hh = __float2half_rn(f);
        uint32_t o = (uint32_t)(j * ROWB + d * 2);
        *(__half*)(sm + OFF_A1H + o) = hh;
        *(__half*)(sm + OFF_A1L + o) = __float2half_rn(f - __half2float(hh));
    }

    float d2[8][4];
#pragma unroll
    for (int i = 0; i < 8; i++)
#pragma unroll
        for (int q = 0; q < 4; q++) d2[i][q] = 0.0f;

    for (int hc = 0; hc < 4; hc++) {
        CP_WAIT1();          // FC(hc) in B0 resident (PJ(hc) may still fly)
        __syncthreads();

        float d1[8][4];
#pragma unroll
        for (int i = 0; i < 8; i++)
#pragma unroll
            for (int q = 0; q < 4; q++) d1[i][q] = 0.0f;
        gemm_2pass(smb + OFF_A1H + aoff, smb + OFF_A1L + aoff,
                   smb + OFF_B0 + boff, d1);
        __syncthreads();     // B0 reads + prev-A2 reads done

        if (hc < 3) {        // FC(hc+1) -> B0
            size_t b = ((size_t)e * HDIM + (hc + 1) * 128) * DE;
            tile_cp(smb + OFF_B0, g_fcw + b, tid);
            CP_COMMIT();
        }

        // epilogue: bias + exact gelu -> A2 hi/lo
#pragma unroll
        for (int mt = 0; mt < 2; mt++)
#pragma unroll
            for (int nt = 0; nt < 4; nt++) {
                float* dv = d1[mt * 4 + nt];
                int col = col0 + nt * 8 + 2 * c;
                float b0 = fcb[e * HDIM + hc * 128 + col];
                float b1 = fcb[e * HDIM + hc * 128 + col + 1];
#pragma unroll
                for (int hrow = 0; hrow < 2; hrow++) {
                    int r = row0 + 16 * mt + g + 8 * hrow;
                    float v0 = dv[2 * hrow] + b0;
                    float v1 = dv[2 * hrow + 1] + b1;
                    v0 = 0.5f * v0 * (1.0f + erff(v0 * 0.70710678118654752440f));
                    v1 = 0.5f * v1 * (1.0f + erff(v1 * 0.70710678118654752440f));
                    __half h0 = __float2half_rn(v0);
                    __half h1 = __float2half_rn(v1);
                    uint32_t o = (uint32_t)(r * ROWB + col * 2);
                    *(uint32_t*)(sm + OFF_A2H + o) =
                        pack2h(__half2float(h0), __half2float(h1));
                    *(uint32_t*)(sm + OFF_A2L + o) =
                        pack2h(v0 - __half2float(h0), v1 - __half2float(h1));
                }
            }

        if (hc < 3) { CP_WAIT1(); } else { CP_WAIT0(); }  // PJ(hc) in B1 ready
        __syncthreads();     // + A2 visible

        gemm_2pass(smb + OFF_A2H + aoff, smb + OFF_A2L + aoff,
                   smb + OFF_B1 + boff, d2);
        __syncthreads();     // B1 reads done

        if (hc < 3) {        // PJ(hc+1) -> B1
            size_t b = (size_t)(e * 4 + hc + 1) * DE * 128;
            tile_cp(smb + OFF_B1, g_pjw + b, tid);
            CP_COMMIT();
        }
    }

    // final: D2 + proj_b -> out (active tokens: gate weight exactly 1)
#pragma unroll
    for (int mt = 0; mt < 2; mt++)
#pragma unroll
        for (int nt = 0; nt < 4; nt++) {
            float* dv = d2[mt * 4 + nt];
            int col = col0 + nt * 8 + 2 * c;
            float b0 = pjb[e * DE + col];
            float b1 = pjb[e * DE + col + 1];
#pragma unroll
            for (int hrow = 0; hrow < 2; hrow++) {
                int r = row0 + 16 * mt + g + 8 * hrow;
                int t = toks[r];
                if (t < 0) continue;
                float2 o;
                o.x = dv[2 * hrow] + b0;
                o.y = dv[2 * hrow + 1] + b1;
                *(float2*)&out[(size_t)t * CDIM + e * DE + col] = o;
            }
        }
}

// ---------------- launch ----------------------------------------------------
extern "C" void kernel_launch(void* const* d_in, const int* in_sizes, int n_in,
                              void* d_out, int out_size)
{
    const float* x   = (const float*)d_in[0];
    const float* gw  = (const float*)d_in[1];
    const float* gb  = (const float*)d_in[2];
    const float* fcw = (const float*)d_in[3];
    const float* fcb = (const float*)d_in[4];
    const float* pjw = (const float*)d_in[5];
    const float* pjb = (const float*)d_in[6];
    float* out = (float*)d_out;

    gate_kernel<<<NTOK / GT, 256>>>(x, gw, gb, out);
    wconv_kernel<<<1024, 256>>>(fcw, pjw);
    dummy_kernel<<<1, 32>>>();   // expert_kernel stays the 4th launch for ncu

    cudaFuncSetAttribute(expert_kernel,
                         cudaFuncAttributeMaxDynamicSharedMemorySize,
                         SMEM_TOTAL);
    dim3 grid(NTOK / MT, NE);
    expert_kernel<<<grid, 512, SMEM_TOTAL>>>(x, fcb, pjb, out);

    cleanup_kernel<<<1, 32>>>();
}